// round 13
// baseline (speedup 1.0000x reference)
#include <cuda_runtime.h>
#include <cuda_bf16.h>
#include <cstdint>

#define CW 2048
#define DIM 128
#define BATCH 8
typedef unsigned long long ull;

__device__ __nv_bfloat16 g_qh[BATCH*CW*DIM], g_ql[BATCH*CW*DIM];
__device__ __nv_bfloat16 g_kh[BATCH*CW*DIM], g_kl[BATCH*CW*DIM];
__device__ __nv_bfloat16 g_vth[BATCH*DIM*CW], g_vtl[BATCH*DIM*CW];
__device__ float g_cos[CW*64], g_sin[CW*64];
__device__ __nv_bfloat16 g_wh[3*DIM*DIM], g_wl[3*DIM*DIM];

// ---- helpers ----
__device__ __forceinline__ uint32_t bf2pack(float lo, float hi){   // low half <- lo
    uint32_t r; asm("cvt.rn.bf16x2.f32 %0, %1, %2;" : "=r"(r) : "f"(hi), "f"(lo)); return r;
}
__device__ __forceinline__ void cpa16s(uint32_t dst, const void* src){
    asm volatile("cp.async.cg.shared.global [%0], [%1], 16;" :: "r"(dst), "l"(src));
}
__device__ __forceinline__ void ldsm4(uint32_t* r, uint32_t a){
    asm volatile("ldmatrix.sync.aligned.m8n8.x4.shared.b16 {%0,%1,%2,%3}, [%4];"
        : "=r"(r[0]),"=r"(r[1]),"=r"(r[2]),"=r"(r[3]) : "r"(a));
}
__device__ __forceinline__ void mma_bf16(float* c, const uint32_t* a, const uint32_t* b){
    asm volatile("mma.sync.aligned.m16n8k16.row.col.f32.bf16.bf16.f32 "
        "{%0,%1,%2,%3}, {%4,%5,%6,%7}, {%8,%9}, {%0,%1,%2,%3};"
        : "+f"(c[0]),"+f"(c[1]),"+f"(c[2]),"+f"(c[3])
        : "r"(a[0]),"r"(a[1]),"r"(a[2]),"r"(a[3]),"r"(b[0]),"r"(b[1]));
}

// ============================================================================
// Kernel P: prep — gather RoPE cos/sin from R's diagonal AND convert W->bf16
// ============================================================================
__global__ void __launch_bounds__(512,2) prep_kernel(
    const float* __restrict__ R, const float* __restrict__ wq,
    const float* __restrict__ wk, const float* __restrict__ wv)
{
    const int g = blockIdx.x, tid = threadIdx.x;
    if (g < 256){
        int idx = g*512 + tid;                    // 0 .. 2048*64-1
        int m = idx >> 6, i = idx & 63;
        const float* base = R + (size_t)m*(DIM*DIM) + i*258;
        g_cos[idx] = base[0];
        g_sin[idx] = base[128];
    } else {
        int idx = (g-256)*512 + tid;              // 0 .. 24575 (pairs)
        int mat = idx >> 13;
        int rem = idx & 8191;
        const float* w = (mat==0)?wq:(mat==1)?wk:wv;
        float2 v = reinterpret_cast<const float2*>(w)[rem];
        uint32_t h = bf2pack(v.x, v.y);
        float h0 = __uint_as_float(h<<16), h1 = __uint_as_float(h & 0xFFFF0000u);
        reinterpret_cast<uint32_t*>(g_wh)[idx] = h;
        reinterpret_cast<uint32_t*>(g_wl)[idx] = bf2pack(v.x - h0, v.y - h1);
    }
}

// ============================================================================
// Kernel A: projection (+RoPE for Q/K) on HMMA. W loaded pre-split via cp.async.
//   One matrix per CTA, 64 rows; grid (32, 8, 3). 2 CTAs/SM.
//   Q is pre-scaled by 1/sqrt(128) so attn needs no scale.
// ============================================================================
#define AST 272
#define A_XH 0
#define A_XL 17408
#define A_WH 34816
#define A_WL 69632
#define SMEM_A 104448

__global__ void __launch_bounds__(256,2) qkv_rope_kernel(const float* __restrict__ x)
{
    extern __shared__ char smc[];
    const uint32_t sb = (uint32_t)__cvta_generic_to_shared(smc);
    const int tid = threadIdx.x, wid = tid>>5, lane = tid&31;
    const int b = blockIdx.y, mbase = blockIdx.x*64, mat = blockIdx.z;
    const int wg = wid & 3;         // m16 tile
    const int nh = wid >> 2;        // n-half (64 cols)
    const int l7 = lane & 7, lhi = lane >> 3;
    const int lg = lane >> 2, lt = lane & 3;

    // ---- W tiles: cp.async of pre-split bf16 ----
    {
        const char* wh = (const char*)g_wh + mat*32768;
        const char* wl = (const char*)g_wl + mat*32768;
        #pragma unroll
        for (int t = 0; t < 8; t++){
            int c = tid + t*256;                  // 2048 16B chunks
            int r = c>>4, cb = (c&15)*16;
            uint32_t dst = sb + A_WH + r*AST + cb;
            cpa16s(dst,                 wh + r*256 + cb);
            cpa16s(dst + (A_WL - A_WH), wl + r*256 + cb);
        }
        asm volatile("cp.async.commit_group;");
    }
    // ---- x tile: load fp32, split hi/lo into smem ----
    {
        const float* xg = x + ((size_t)b*CW + mbase)*DIM;
        uint32_t* xh = reinterpret_cast<uint32_t*>(smc);
        #pragma unroll
        for (int t = 0; t < 16; t++){
            int idx = tid + t*256;                // 4096 col-pairs
            int r = idx>>6, cp = idx&63;
            float2 v = *reinterpret_cast<const float2*>(xg + r*DIM + 2*cp);
            uint32_t h = bf2pack(v.x, v.y);
            float h0 = __uint_as_float(h<<16), h1 = __uint_as_float(h & 0xFFFF0000u);
            uint32_t off = (uint32_t)(r*AST + cp*4) >> 2;
            xh[(A_XH>>2) + off] = h;
            xh[(A_XL>>2) + off] = bf2pack(v.x - h0, v.y - h1);
        }
    }
    asm volatile("cp.async.wait_group 0;");
    __syncthreads();

    // ---- x A-fragments (8 k-chunks, hi+lo) ----
    uint32_t xhf[8][4], xlf[8][4];
    {
        uint32_t xa = sb + A_XH + (16*wg + (lane&15))*AST + (lane>>4)*16;
        #pragma unroll
        for (int c = 0; c < 8; c++){
            ldsm4(xhf[c], xa + c*32);
            ldsm4(xlf[c], xa + (A_XL - A_XH) + c*32);
        }
    }

    // ---- GEMM: out[m16, n64] = x @ W^T, 3-term ----
    float s[8][4];
    #pragma unroll
    for (int j = 0; j < 8; j++){ s[j][0]=s[j][1]=s[j][2]=s[j][3]=0.0f; }
    #pragma unroll
    for (int j = 0; j < 8; j++){
        const int jj = 8*nh + j;
        uint32_t wa = sb + A_WH + (8*jj + l7)*AST + lhi*16;
        #pragma unroll
        for (int c2 = 0; c2 < 4; c2++){
            uint32_t th[4], tl[4];
            ldsm4(th, wa + c2*64);
            ldsm4(tl, wa + (A_WL - A_WH) + c2*64);
            uint32_t bhA[2]={th[0],th[1]}, bhB[2]={th[2],th[3]};
            uint32_t blA[2]={tl[0],tl[1]}, blB[2]={tl[2],tl[3]};
            mma_bf16(s[j], xhf[2*c2],   bhA);
            mma_bf16(s[j], xhf[2*c2+1], bhB);
            mma_bf16(s[j], xhf[2*c2],   blA);
            mma_bf16(s[j], xhf[2*c2+1], blB);
            mma_bf16(s[j], xlf[2*c2],   bhA);
            mma_bf16(s[j], xlf[2*c2+1], bhB);
        }
    }

    // ---- epilogue ----
    const int r0 = 16*wg + lg;                 // local row (c0/c1); c2/c3: +8
    if (mat < 2){   // Q/K: RoPE + (Q only) 1/sqrt(128) scale + hi/lo split
        const float qsc = (mat==0) ? 0.08838834764831845f : 1.0f;
        uint32_t* gh = reinterpret_cast<uint32_t*>(mat==0 ? g_qh : g_kh);
        uint32_t* gl = reinterpret_cast<uint32_t*>(mat==0 ? g_ql : g_kl);
        const int m0 = mbase + r0, m1 = m0 + 8;
        const float* cr0 = g_cos + (size_t)m0*64;
        const float* sr0 = g_sin + (size_t)m0*64;
        const float* cr1 = g_cos + (size_t)m1*64;
        const float* sr1 = g_sin + (size_t)m1*64;
        size_t rp0 = ((size_t)b*CW + m0)*64, rp1 = ((size_t)b*CW + m1)*64;
        #pragma unroll
        for (int j = 0; j < 8; j++){
            const int i = 32*nh + 4*j + lt;    // rotation pair index
            float c0 = __ldg(cr0 + i), s0 = __ldg(sr0 + i);
            float c1 = __ldg(cr1 + i), s1 = __ldg(sr1 + i);
            float a0 = ( s[j][0]*c0 + s[j][1]*s0)*qsc;
            float a1 = (-s[j][0]*s0 + s[j][1]*c0)*qsc;
            float b0 = ( s[j][2]*c1 + s[j][3]*s1)*qsc;
            float b1 = (-s[j][2]*s1 + s[j][3]*c1)*qsc;
            uint32_t ha = bf2pack(a0, a1);
            float ha0 = __uint_as_float(ha<<16), ha1 = __uint_as_float(ha & 0xFFFF0000u);
            gh[rp0 + i] = ha;
            gl[rp0 + i] = bf2pack(a0-ha0, a1-ha1);
            uint32_t hb = bf2pack(b0, b1);
            float hb0 = __uint_as_float(hb<<16), hb1 = __uint_as_float(hb & 0xFFFF0000u);
            gh[rp1 + i] = hb;
            gl[rp1 + i] = bf2pack(b0-hb0, b1-hb1);
        }
    } else {        // V: transpose via smem staging (overlaid on x region)
        __syncthreads();   // x fragment reads done
        unsigned short* vth_s = reinterpret_cast<unsigned short*>(smc);
        unsigned short* vtl_s = vth_s + 128*66;
        #pragma unroll
        for (int j = 0; j < 8; j++){
            const int d0 = 64*nh + 8*j + 2*lt;   // even d; odd = d0+1
            uint32_t h = bf2pack(s[j][0], s[j][1]);
            float h0 = __uint_as_float(h<<16), h1 = __uint_as_float(h & 0xFFFF0000u);
            uint32_t l = bf2pack(s[j][0]-h0, s[j][1]-h1);
            vth_s[d0*66 + r0]     = (unsigned short)(h & 0xFFFF);
            vth_s[(d0+1)*66 + r0] = (unsigned short)(h >> 16);
            vtl_s[d0*66 + r0]     = (unsigned short)(l & 0xFFFF);
            vtl_s[(d0+1)*66 + r0] = (unsigned short)(l >> 16);
            uint32_t g = bf2pack(s[j][2], s[j][3]);
            float g0 = __uint_as_float(g<<16), g1 = __uint_as_float(g & 0xFFFF0000u);
            uint32_t m = bf2pack(s[j][2]-g0, s[j][3]-g1);
            vth_s[d0*66 + r0+8]     = (unsigned short)(g & 0xFFFF);
            vth_s[(d0+1)*66 + r0+8] = (unsigned short)(g >> 16);
            vtl_s[d0*66 + r0+8]     = (unsigned short)(m & 0xFFFF);
            vtl_s[(d0+1)*66 + r0+8] = (unsigned short)(m >> 16);
        }
        __syncthreads();
        uint32_t* gh = reinterpret_cast<uint32_t*>(g_vth);
        uint32_t* gl = reinterpret_cast<uint32_t*>(g_vtl);
        for (int idx = tid; idx < 128*32; idx += 256){
            int d = idx>>5, mp = idx&31;
            size_t dst = ((size_t)(b*DIM + d)*CW + mbase)/2 + mp;
            gh[dst] = *reinterpret_cast<uint32_t*>(&vth_s[d*66 + 2*mp]);
            gl[dst] = *reinterpret_cast<uint32_t*>(&vtl_s[d*66 + 2*mp]);
        }
    }
}

// ============================================================================
// Kernel B: HMMA flash attention, BM=64, 512 threads / 16 warps:
//   4 row-blocks x 4 k-quarters. Q pre-scaled. Single-stage 3-buffer combine.
// ============================================================================
#define STK 272
#define STV 144
#define KBYTES (64*STK)
#define VBYTES (128*STV)
#define QBYTES (64*STK)
#define OFF_Q  0
#define OFF_B0 (2*QBYTES)
#define OFF_B1 (OFF_B0 + 2*KBYTES + 2*VBYTES)
#define OFF_LR (OFF_B1 + 2*KBYTES + 2*VBYTES)
#define SMEM_BB (OFF_LR + 1024)
#define REDSZ (64*132*4)

__device__ __forceinline__ void load_kv_stage(uint32_t sb, int b, int kt, int buf, int tid){
    const char* kh = (const char*)(g_kh  + ((size_t)b*CW + kt*64)*DIM);
    const char* kl = (const char*)(g_kl  + ((size_t)b*CW + kt*64)*DIM);
    const char* vh = (const char*)(g_vth + (size_t)b*DIM*CW + kt*64);
    const char* vl = (const char*)(g_vtl + (size_t)b*DIM*CW + kt*64);
    uint32_t bo = sb + (buf ? OFF_B1 : OFF_B0);
    #pragma unroll
    for (int t = 0; t < 2; t++){
        int c = tid + t*512;                   // K: 64 rows x 16 chunks
        int n = c>>4, cb = (c&15)*16;
        uint32_t dst = bo + n*STK + cb;
        cpa16s(dst,          kh + n*256 + cb);
        cpa16s(dst + KBYTES, kl + n*256 + cb);
    }
    #pragma unroll
    for (int t = 0; t < 2; t++){
        int c = tid + t*512;                   // V^T: 128 rows x 8 chunks
        int d = c>>3, cb = (c&7)*16;
        uint32_t dst = bo + 2*KBYTES + d*STV + cb;
        cpa16s(dst,          vh + (size_t)d*CW*2 + cb);
        cpa16s(dst + VBYTES, vl + (size_t)d*CW*2 + cb);
    }
}

__global__ void __launch_bounds__(512,1) attn_hmma_kernel(float* __restrict__ out)
{
    extern __shared__ char smc[];
    const uint32_t sb = (uint32_t)__cvta_generic_to_shared(smc);
    const int tid = threadIdx.x, wid = tid>>5, lane = tid&31;
    const int b = blockIdx.x & 7;
    const int qt = 31 - ((int)blockIdx.x >> 3);    // heavy q-tiles first
    const int qbase = qt*64;
    const int ktmax = qt;
    const int wg = wid & 3;                         // row block (16 rows)
    const int nh = wid >> 2;                        // k-quarter (0..3, 16 cols)
    const int l7 = lane & 7;
    const int lg = lane >> 2, lt = lane & 3;
    const int row0 = 16*wg + lg;

    // ---- prologue: stage Q + K/V tile0 ----
    {
        const char* qh = (const char*)(g_qh + ((size_t)b*CW + qbase)*DIM);
        const char* ql = (const char*)(g_ql + ((size_t)b*CW + qbase)*DIM);
        #pragma unroll
        for (int t = 0; t < 2; t++){
            int c = tid + t*512;
            int n = c>>4, cb = (c&15)*16;
            uint32_t dst = sb + OFF_Q + n*STK + cb;
            cpa16s(dst,          qh + n*256 + cb);
            cpa16s(dst + QBYTES, ql + n*256 + cb);
        }
        asm volatile("cp.async.commit_group;");
        load_kv_stage(sb, b, 0, 0, tid);
        asm volatile("cp.async.commit_group;");
    }
    asm volatile("cp.async.wait_group 1;");
    __syncthreads();

    float o[16][4];
    #pragma unroll
    for (int jd = 0; jd < 16; jd++){
        #pragma unroll
        for (int i = 0; i < 4; i++) o[jd][i] = 0.0f;
    }
    float lsum0 = 0.0f, lsum1 = 0.0f;

    // lane-invariant address parts
    const uint32_t qa = sb + OFF_Q + (16*wg + (lane&15))*STK + (lane>>4)*16;
    const uint32_t krow = (uint32_t)((8*(2*nh + (lane>>4)) + l7)*STK + ((lane>>3)&1)*16);
    const uint32_t vrow = (uint32_t)((((lane>>4)*8 + l7))*STV + nh*32 + ((lane>>3)&1)*16);

    for (int kt = 0; kt <= ktmax; kt++){
        __syncthreads();                            // prior reads of buf[(kt+1)&1] done
        if (kt < ktmax) load_kv_stage(sb, b, kt+1, (kt+1)&1, tid);
        asm volatile("cp.async.commit_group;");
        asm volatile("cp.async.wait_group 1;");     // stage kt landed
        __syncthreads();

        const uint32_t bo = sb + ((kt&1) ? OFF_B1 : OFF_B0);
        const uint32_t ka = bo + krow;              // khs; kls = +KBYTES
        const uint32_t va = bo + 2*KBYTES + vrow;   // vhs; vls = +VBYTES

        // ---- S = Q K^T over this warp's 16 cols (2 n-tiles), 2 chains ----
        float shh[2][4], sxx[2][4];
        #pragma unroll
        for (int j = 0; j < 2; j++){
            #pragma unroll
            for (int i = 0; i < 4; i++){ shh[j][i] = 0.0f; sxx[j][i] = 0.0f; }
        }
        #pragma unroll
        for (int c = 0; c < 8; c++){
            uint32_t ah[4], al[4], th[4], tl[4];
            ldsm4(ah, qa + c*32);
            ldsm4(al, qa + QBYTES + c*32);
            ldsm4(th, ka + c*32);
            ldsm4(tl, ka + KBYTES + c*32);
            uint32_t bh0[2]={th[0],th[1]}, bh1[2]={th[2],th[3]};
            uint32_t bl0[2]={tl[0],tl[1]}, bl1[2]={tl[2],tl[3]};
            mma_bf16(shh[0], ah, bh0);
            mma_bf16(sxx[0], ah, bl0);
            mma_bf16(sxx[0], al, bh0);
            mma_bf16(shh[1], ah, bh1);
            mma_bf16(sxx[1], ah, bl1);
            mma_bf16(sxx[1], al, bh1);
        }

        // ---- softmax (unnormalized; Q pre-scaled) + repack into P fragment ----
        const bool domask = (kt == ktmax);
        uint32_t ph[4], pl[4];
        #pragma unroll
        for (int j = 0; j < 2; j++){
            const int colLoc = 16*nh + 8*j + 2*lt;
            float p0 = __expf(shh[j][0] + sxx[j][0]);
            float p1 = __expf(shh[j][1] + sxx[j][1]);
            float p2 = __expf(shh[j][2] + sxx[j][2]);
            float p3 = __expf(shh[j][3] + sxx[j][3]);
            if (domask){
                if (colLoc   > row0)     p0 = 0.0f;
                if (colLoc+1 > row0)     p1 = 0.0f;
                if (colLoc   > row0+8)   p2 = 0.0f;
                if (colLoc+1 > row0+8)   p3 = 0.0f;
            }
            lsum0 += p0 + p1;
            lsum1 += p2 + p3;
            uint32_t h01 = bf2pack(p0, p1), h23 = bf2pack(p2, p3);
            float h0 = __uint_as_float(h01<<16), h1 = __uint_as_float(h01 & 0xFFFF0000u);
            float h2 = __uint_as_float(h23<<16), h3 = __uint_as_float(h23 & 0xFFFF0000u);
            ph[2*j]   = h01; ph[2*j+1] = h23;
            pl[2*j]   = bf2pack(p0-h0, p1-h1);
            pl[2*j+1] = bf2pack(p2-h2, p3-h3);
        }

        // ---- O += P V over this warp's 16 keys ----
        #pragma unroll
        for (int jp = 0; jp < 8; jp++){
            uint32_t tv[4], tw[4];
            ldsm4(tv, va + jp*(16*STV));
            ldsm4(tw, va + VBYTES + jp*(16*STV));
            uint32_t vh0[2]={tv[0],tv[1]}, vh1[2]={tv[2],tv[3]};
            uint32_t vl0[2]={tw[0],tw[1]}, vl1[2]={tw[2],tw[3]};
            mma_bf16(o[2*jp],   ph, vh0);
            mma_bf16(o[2*jp],   ph, vl0);
            mma_bf16(o[2*jp],   pl, vh0);
            mma_bf16(o[2*jp+1], ph, vh1);
            mma_bf16(o[2*jp+1], ph, vl1);
            mma_bf16(o[2*jp+1], pl, vh1);
        }
    }

    // ---- single-stage 3-buffer combine of partial O / lsum ----
    lsum0 += __shfl_xor_sync(0xffffffffu, lsum0, 1);
    lsum0 += __shfl_xor_sync(0xffffffffu, lsum0, 2);
    lsum1 += __shfl_xor_sync(0xffffffffu, lsum1, 1);
    lsum1 += __shfl_xor_sync(0xffffffffu, lsum1, 2);

    float* red = reinterpret_cast<float*>(smc + OFF_B0);   // 3 x [64][132]
    float* lr  = reinterpret_cast<float*>(smc + OFF_LR);   // 3 x [64]

    __syncthreads();                               // all KV-buf reads done; reuse
    if (nh != 0){
        float* dst = red + (nh-1)*(64*132);
        float* lrd = lr  + (nh-1)*64;
        #pragma unroll
        for (int jd = 0; jd < 16; jd++){
            int col = 8*jd + 2*lt;
            *reinterpret_cast<float2*>(&dst[row0*132 + col])     = make_float2(o[jd][0], o[jd][1]);
            *reinterpret_cast<float2*>(&dst[(row0+8)*132 + col]) = make_float2(o[jd][2], o[jd][3]);
        }
        if (lt == 0){ lrd[row0] = lsum0; lrd[row0+8] = lsum1; }
    }
    __syncthreads();
    if (nh == 0){
        const float li0 = 1.0f / (lsum0 + lr[row0]       + lr[64+row0]       + lr[128+row0]);
        const float li1 = 1.0f / (lsum1 + lr[row0+8]     + lr[64+row0+8]     + lr[128+row0+8]);
        float* og0 = out + ((size_t)b*CW + qbase + row0)*DIM;
        float* og1 = og0 + 8*DIM;
        #pragma unroll
        for (int jd = 0; jd < 16; jd++){
            int col = 8*jd + 2*lt;
            float2 a0 = *reinterpret_cast<float2*>(&red[row0*132 + col]);
            float2 a1 = *reinterpret_cast<float2*>(&red[64*132 + row0*132 + col]);
            float2 a2 = *reinterpret_cast<float2*>(&red[2*64*132 + row0*132 + col]);
            float2 c0 = *reinterpret_cast<float2*>(&red[(row0+8)*132 + col]);
            float2 c1 = *reinterpret_cast<float2*>(&red[64*132 + (row0+8)*132 + col]);
            float2 c2 = *reinterpret_cast<float2*>(&red[2*64*132 + (row0+8)*132 + col]);
            *reinterpret_cast<float2*>(og0 + col) =
                make_float2((o[jd][0]+a0.x+a1.x+a2.x)*li0, (o[jd][1]+a0.y+a1.y+a2.y)*li0);
            *reinterpret_cast<float2*>(og1 + col) =
                make_float2((o[jd][2]+c0.x+c1.x+c2.x)*li1, (o[jd][3]+c0.y+c1.y+c2.y)*li1);
        }
    }
}

// ============================================================================
extern "C" void kernel_launch(void* const* d_in, const int* in_sizes, int n_in,
                              void* d_out, int out_size)
{
    (void)in_sizes; (void)n_in; (void)out_size;
    const float* x  = (const float*)d_in[0];
    const float* wq = (const float*)d_in[1];
    const float* wk = (const float*)d_in[2];
    const float* wv = (const float*)d_in[3];
    const float* R  = (const float*)d_in[4];
    float* out = (float*)d_out;

    cudaFuncSetAttribute(qkv_rope_kernel,   cudaFuncAttributeMaxDynamicSharedMemorySize, SMEM_A);
    cudaFuncSetAttribute(attn_hmma_kernel,  cudaFuncAttributeMaxDynamicSharedMemorySize, SMEM_BB);

    prep_kernel<<<304, 512>>>(R, wq, wk, wv);
    qkv_rope_kernel<<<dim3(32, BATCH, 3), 256, SMEM_A>>>(x);
    attn_hmma_kernel<<<256, 512, SMEM_BB>>>(out);
}

// round 15
// speedup vs baseline: 1.0326x; 1.0326x over previous
#include <cuda_runtime.h>
#include <cuda_bf16.h>
#include <cstdint>

#define CW 2048
#define DIM 128
#define BATCH 8
typedef unsigned long long ull;

__device__ __nv_bfloat16 g_qh[BATCH*CW*DIM], g_ql[BATCH*CW*DIM];
__device__ __nv_bfloat16 g_kh[BATCH*CW*DIM], g_kl[BATCH*CW*DIM];
__device__ __nv_bfloat16 g_vth[BATCH*DIM*CW], g_vtl[BATCH*DIM*CW];
__device__ float g_cos[CW*64], g_sin[CW*64];
__device__ __nv_bfloat16 g_wh[3*DIM*DIM], g_wl[3*DIM*DIM];

// ---- helpers ----
__device__ __forceinline__ uint32_t bf2pack(float lo, float hi){   // low half <- lo
    uint32_t r; asm("cvt.rn.bf16x2.f32 %0, %1, %2;" : "=r"(r) : "f"(hi), "f"(lo)); return r;
}
__device__ __forceinline__ void cpa16s(uint32_t dst, const void* src){
    asm volatile("cp.async.cg.shared.global [%0], [%1], 16;" :: "r"(dst), "l"(src));
}
__device__ __forceinline__ void ldsm4(uint32_t* r, uint32_t a){
    asm volatile("ldmatrix.sync.aligned.m8n8.x4.shared.b16 {%0,%1,%2,%3}, [%4];"
        : "=r"(r[0]),"=r"(r[1]),"=r"(r[2]),"=r"(r[3]) : "r"(a));
}
__device__ __forceinline__ void mma_bf16(float* c, const uint32_t* a, const uint32_t* b){
    asm volatile("mma.sync.aligned.m16n8k16.row.col.f32.bf16.bf16.f32 "
        "{%0,%1,%2,%3}, {%4,%5,%6,%7}, {%8,%9}, {%0,%1,%2,%3};"
        : "+f"(c[0]),"+f"(c[1]),"+f"(c[2]),"+f"(c[3])
        : "r"(a[0]),"r"(a[1]),"r"(a[2]),"r"(a[3]),"r"(b[0]),"r"(b[1]));
}

// ============================================================================
// Kernel P: prep — gather RoPE cos/sin from R's diagonal AND convert W->bf16
// ============================================================================
__global__ void __launch_bounds__(512,2) prep_kernel(
    const float* __restrict__ R, const float* __restrict__ wq,
    const float* __restrict__ wk, const float* __restrict__ wv)
{
    const int g = blockIdx.x, tid = threadIdx.x;
    if (g < 256){
        int idx = g*512 + tid;                    // 0 .. 2048*64-1
        int m = idx >> 6, i = idx & 63;
        const float* base = R + (size_t)m*(DIM*DIM) + i*258;
        g_cos[idx] = base[0];
        g_sin[idx] = base[128];
    } else {
        int idx = (g-256)*512 + tid;              // 0 .. 24575 (pairs)
        int mat = idx >> 13;
        int rem = idx & 8191;
        const float* w = (mat==0)?wq:(mat==1)?wk:wv;
        float2 v = reinterpret_cast<const float2*>(w)[rem];
        uint32_t h = bf2pack(v.x, v.y);
        float h0 = __uint_as_float(h<<16), h1 = __uint_as_float(h & 0xFFFF0000u);
        reinterpret_cast<uint32_t*>(g_wh)[idx] = h;
        reinterpret_cast<uint32_t*>(g_wl)[idx] = bf2pack(v.x - h0, v.y - h1);
    }
}

// ============================================================================
// Kernel A: projection (+RoPE for Q/K) on HMMA (unchanged from R13)
// ============================================================================
#define AST 272
#define A_XH 0
#define A_XL 17408
#define A_WH 34816
#define A_WL 69632
#define SMEM_A 104448

__global__ void __launch_bounds__(256,2) qkv_rope_kernel(const float* __restrict__ x)
{
    extern __shared__ char smc[];
    const uint32_t sb = (uint32_t)__cvta_generic_to_shared(smc);
    const int tid = threadIdx.x, wid = tid>>5, lane = tid&31;
    const int b = blockIdx.y, mbase = blockIdx.x*64, mat = blockIdx.z;
    const int wg = wid & 3;
    const int nh = wid >> 2;
    const int l7 = lane & 7, lhi = lane >> 3;
    const int lg = lane >> 2, lt = lane & 3;

    {
        const char* wh = (const char*)g_wh + mat*32768;
        const char* wl = (const char*)g_wl + mat*32768;
        #pragma unroll
        for (int t = 0; t < 8; t++){
            int c = tid + t*256;
            int r = c>>4, cb = (c&15)*16;
            uint32_t dst = sb + A_WH + r*AST + cb;
            cpa16s(dst,                 wh + r*256 + cb);
            cpa16s(dst + (A_WL - A_WH), wl + r*256 + cb);
        }
        asm volatile("cp.async.commit_group;");
    }
    {
        const float* xg = x + ((size_t)b*CW + mbase)*DIM;
        uint32_t* xh = reinterpret_cast<uint32_t*>(smc);
        #pragma unroll
        for (int t = 0; t < 16; t++){
            int idx = tid + t*256;
            int r = idx>>6, cp = idx&63;
            float2 v = *reinterpret_cast<const float2*>(xg + r*DIM + 2*cp);
            uint32_t h = bf2pack(v.x, v.y);
            float h0 = __uint_as_float(h<<16), h1 = __uint_as_float(h & 0xFFFF0000u);
            uint32_t off = (uint32_t)(r*AST + cp*4) >> 2;
            xh[(A_XH>>2) + off] = h;
            xh[(A_XL>>2) + off] = bf2pack(v.x - h0, v.y - h1);
        }
    }
    asm volatile("cp.async.wait_group 0;");
    __syncthreads();

    uint32_t xhf[8][4], xlf[8][4];
    {
        uint32_t xa = sb + A_XH + (16*wg + (lane&15))*AST + (lane>>4)*16;
        #pragma unroll
        for (int c = 0; c < 8; c++){
            ldsm4(xhf[c], xa + c*32);
            ldsm4(xlf[c], xa + (A_XL - A_XH) + c*32);
        }
    }

    float s[8][4];
    #pragma unroll
    for (int j = 0; j < 8; j++){ s[j][0]=s[j][1]=s[j][2]=s[j][3]=0.0f; }
    #pragma unroll
    for (int j = 0; j < 8; j++){
        const int jj = 8*nh + j;
        uint32_t wa = sb + A_WH + (8*jj + l7)*AST + lhi*16;
        #pragma unroll
        for (int c2 = 0; c2 < 4; c2++){
            uint32_t th[4], tl[4];
            ldsm4(th, wa + c2*64);
            ldsm4(tl, wa + (A_WL - A_WH) + c2*64);
            uint32_t bhA[2]={th[0],th[1]}, bhB[2]={th[2],th[3]};
            uint32_t blA[2]={tl[0],tl[1]}, blB[2]={tl[2],tl[3]};
            mma_bf16(s[j], xhf[2*c2],   bhA);
            mma_bf16(s[j], xhf[2*c2+1], bhB);
            mma_bf16(s[j], xhf[2*c2],   blA);
            mma_bf16(s[j], xhf[2*c2+1], blB);
            mma_bf16(s[j], xlf[2*c2],   bhA);
            mma_bf16(s[j], xlf[2*c2+1], bhB);
        }
    }

    const int r0 = 16*wg + lg;
    if (mat < 2){
        const float qsc = (mat==0) ? 0.08838834764831845f : 1.0f;
        uint32_t* gh = reinterpret_cast<uint32_t*>(mat==0 ? g_qh : g_kh);
        uint32_t* gl = reinterpret_cast<uint32_t*>(mat==0 ? g_ql : g_kl);
        const int m0 = mbase + r0, m1 = m0 + 8;
        const float* cr0 = g_cos + (size_t)m0*64;
        const float* sr0 = g_sin + (size_t)m0*64;
        const float* cr1 = g_cos + (size_t)m1*64;
        const float* sr1 = g_sin + (size_t)m1*64;
        size_t rp0 = ((size_t)b*CW + m0)*64, rp1 = ((size_t)b*CW + m1)*64;
        #pragma unroll
        for (int j = 0; j < 8; j++){
            const int i = 32*nh + 4*j + lt;
            float c0 = __ldg(cr0 + i), s0 = __ldg(sr0 + i);
            float c1 = __ldg(cr1 + i), s1 = __ldg(sr1 + i);
            float a0 = ( s[j][0]*c0 + s[j][1]*s0)*qsc;
            float a1 = (-s[j][0]*s0 + s[j][1]*c0)*qsc;
            float b0 = ( s[j][2]*c1 + s[j][3]*s1)*qsc;
            float b1 = (-s[j][2]*s1 + s[j][3]*c1)*qsc;
            uint32_t ha = bf2pack(a0, a1);
            float ha0 = __uint_as_float(ha<<16), ha1 = __uint_as_float(ha & 0xFFFF0000u);
            gh[rp0 + i] = ha;
            gl[rp0 + i] = bf2pack(a0-ha0, a1-ha1);
            uint32_t hb = bf2pack(b0, b1);
            float hb0 = __uint_as_float(hb<<16), hb1 = __uint_as_float(hb & 0xFFFF0000u);
            gh[rp1 + i] = hb;
            gl[rp1 + i] = bf2pack(b0-hb0, b1-hb1);
        }
    } else {
        __syncthreads();
        unsigned short* vth_s = reinterpret_cast<unsigned short*>(smc);
        unsigned short* vtl_s = vth_s + 128*66;
        #pragma unroll
        for (int j = 0; j < 8; j++){
            const int d0 = 64*nh + 8*j + 2*lt;
            uint32_t h = bf2pack(s[j][0], s[j][1]);
            float h0 = __uint_as_float(h<<16), h1 = __uint_as_float(h & 0xFFFF0000u);
            uint32_t l = bf2pack(s[j][0]-h0, s[j][1]-h1);
            vth_s[d0*66 + r0]     = (unsigned short)(h & 0xFFFF);
            vth_s[(d0+1)*66 + r0] = (unsigned short)(h >> 16);
            vtl_s[d0*66 + r0]     = (unsigned short)(l & 0xFFFF);
            vtl_s[(d0+1)*66 + r0] = (unsigned short)(l >> 16);
            uint32_t g = bf2pack(s[j][2], s[j][3]);
            float g0 = __uint_as_float(g<<16), g1 = __uint_as_float(g & 0xFFFF0000u);
            uint32_t m = bf2pack(s[j][2]-g0, s[j][3]-g1);
            vth_s[d0*66 + r0+8]     = (unsigned short)(g & 0xFFFF);
            vth_s[(d0+1)*66 + r0+8] = (unsigned short)(g >> 16);
            vtl_s[d0*66 + r0+8]     = (unsigned short)(m & 0xFFFF);
            vtl_s[(d0+1)*66 + r0+8] = (unsigned short)(m >> 16);
        }
        __syncthreads();
        uint32_t* gh = reinterpret_cast<uint32_t*>(g_vth);
        uint32_t* gl = reinterpret_cast<uint32_t*>(g_vtl);
        for (int idx = tid; idx < 128*32; idx += 256){
            int d = idx>>5, mp = idx&31;
            size_t dst = ((size_t)(b*DIM + d)*CW + mbase)/2 + mp;
            gh[dst] = *reinterpret_cast<uint32_t*>(&vth_s[d*66 + 2*mp]);
            gl[dst] = *reinterpret_cast<uint32_t*>(&vtl_s[d*66 + 2*mp]);
        }
    }
}

// ============================================================================
// Kernel B: HMMA flash attention, BM=64, 16 warps:
//   QK: warp (wg, nh) does k-quarter nh with PERSISTENT Q regs.
//   P exchanged via smem; PV: warp (wg, nh) does d-quarter nh over full k.
//   Output slices disjoint -> no O combine; only lsum reduced.
// ============================================================================
#define STK 272
#define STV 144
#define PST 144
#define KBYTES (64*STK)
#define VBYTES (128*STV)
#define QBYTES (64*STK)
#define OFF_Q  0
#define OFF_B0 (2*QBYTES)
#define OFF_B1 (OFF_B0 + 2*KBYTES + 2*VBYTES)
#define OFF_LR (OFF_B1 + 2*KBYTES + 2*VBYTES)
#define OFF_PH (OFF_LR + 1024)
#define OFF_PL (OFF_PH + 64*PST)
#define SMEM_BB (OFF_PL + 64*PST)

__device__ __forceinline__ void load_kv_stage(uint32_t sb, int b, int kt, int buf, int tid){
    const char* kh = (const char*)(g_kh  + ((size_t)b*CW + kt*64)*DIM);
    const char* kl = (const char*)(g_kl  + ((size_t)b*CW + kt*64)*DIM);
    const char* vh = (const char*)(g_vth + (size_t)b*DIM*CW + kt*64);
    const char* vl = (const char*)(g_vtl + (size_t)b*DIM*CW + kt*64);
    uint32_t bo = sb + (buf ? OFF_B1 : OFF_B0);
    #pragma unroll
    for (int t = 0; t < 2; t++){
        int c = tid + t*512;                   // K: 64 rows x 16 chunks
        int n = c>>4, cb = (c&15)*16;
        uint32_t dst = bo + n*STK + cb;
        cpa16s(dst,          kh + n*256 + cb);
        cpa16s(dst + KBYTES, kl + n*256 + cb);
    }
    #pragma unroll
    for (int t = 0; t < 2; t++){
        int c = tid + t*512;                   // V^T: 128 rows x 8 chunks
        int d = c>>3, cb = (c&7)*16;
        uint32_t dst = bo + 2*KBYTES + d*STV + cb;
        cpa16s(dst,          vh + (size_t)d*CW*2 + cb);
        cpa16s(dst + VBYTES, vl + (size_t)d*CW*2 + cb);
    }
}

__global__ void __launch_bounds__(512,1) attn_hmma_kernel(float* __restrict__ out)
{
    extern __shared__ char smc[];
    const uint32_t sb = (uint32_t)__cvta_generic_to_shared(smc);
    const int tid = threadIdx.x, wid = tid>>5, lane = tid&31;
    const int b = blockIdx.x & 7;
    const int qt = 31 - ((int)blockIdx.x >> 3);    // heavy q-tiles first
    const int qbase = qt*64;
    const int ktmax = qt;
    const int wg = wid & 3;                         // row block (16 rows)
    const int nh = wid >> 2;                        // k-quarter (QK) / d-quarter (PV)
    const int l7 = lane & 7;
    const int lg = lane >> 2, lt = lane & 3;
    const int row0 = 16*wg + lg;

    // ---- prologue: stage Q + K/V tile0 ----
    {
        const char* qh = (const char*)(g_qh + ((size_t)b*CW + qbase)*DIM);
        const char* ql = (const char*)(g_ql + ((size_t)b*CW + qbase)*DIM);
        #pragma unroll
        for (int t = 0; t < 2; t++){
            int c = tid + t*512;
            int n = c>>4, cb = (c&15)*16;
            uint32_t dst = sb + OFF_Q + n*STK + cb;
            cpa16s(dst,          qh + n*256 + cb);
            cpa16s(dst + QBYTES, ql + n*256 + cb);
        }
        asm volatile("cp.async.commit_group;");
        load_kv_stage(sb, b, 0, 0, tid);
        asm volatile("cp.async.commit_group;");
    }
    asm volatile("cp.async.wait_group 1;");        // Q landed
    __syncthreads();

    // ---- persistent Q A-fragments (8 k-chunks, hi+lo) ----
    uint32_t ah[8][4], al[8][4];
    {
        uint32_t qa = sb + OFF_Q + (16*wg + (lane&15))*STK + (lane>>4)*16;
        #pragma unroll
        for (int c = 0; c < 8; c++){
            ldsm4(ah[c], qa + c*32);
            ldsm4(al[c], qa + QBYTES + c*32);
        }
    }

    float o[4][4];
    #pragma unroll
    for (int jd = 0; jd < 4; jd++){
        #pragma unroll
        for (int i = 0; i < 4; i++) o[jd][i] = 0.0f;
    }
    float lsum0 = 0.0f, lsum1 = 0.0f;

    // lane-invariant address parts
    const uint32_t krow = (uint32_t)((8*(2*nh + (lane>>4)) + l7)*STK + ((lane>>3)&1)*16);
    const uint32_t vrow = (uint32_t)(((lane>>4)*8 + l7 + 32*nh)*STV + ((lane>>3)&1)*16);
    const uint32_t pra  = (uint32_t)((16*wg + (lane&15))*PST + (lane>>4)*16);
    const uint32_t pa_h = sb + OFF_PH + pra;
    const uint32_t pa_l = sb + OFF_PL + pra;

    for (int kt = 0; kt <= ktmax; kt++){
        __syncthreads();                            // prior reads of buf[(kt+1)&1] done
        if (kt < ktmax) load_kv_stage(sb, b, kt+1, (kt+1)&1, tid);
        asm volatile("cp.async.commit_group;");
        asm volatile("cp.async.wait_group 1;");     // stage kt landed
        __syncthreads();

        const uint32_t bo = sb + ((kt&1) ? OFF_B1 : OFF_B0);
        const uint32_t ka = bo + krow;

        // ---- S = Q K^T over this warp's k-quarter (16 cols), 2 chains ----
        float shh[2][4], sxx[2][4];
        #pragma unroll
        for (int j = 0; j < 2; j++){
            #pragma unroll
            for (int i = 0; i < 4; i++){ shh[j][i] = 0.0f; sxx[j][i] = 0.0f; }
        }
        #pragma unroll
        for (int c = 0; c < 8; c++){
            uint32_t th[4], tl[4];
            ldsm4(th, ka + c*32);
            ldsm4(tl, ka + KBYTES + c*32);
            uint32_t bh0[2]={th[0],th[1]}, bh1[2]={th[2],th[3]};
            uint32_t bl0[2]={tl[0],tl[1]}, bl1[2]={tl[2],tl[3]};
            mma_bf16(shh[0], ah[c], bh0);
            mma_bf16(sxx[0], ah[c], bl0);
            mma_bf16(sxx[0], al[c], bh0);
            mma_bf16(shh[1], ah[c], bh1);
            mma_bf16(sxx[1], ah[c], bl1);
            mma_bf16(sxx[1], al[c], bh1);
        }

        // ---- softmax (unnormalized; Q pre-scaled) -> P hi/lo into smem ----
        const bool domask = (kt == ktmax);
        #pragma unroll
        for (int j = 0; j < 2; j++){
            const int colLoc = 16*nh + 8*j + 2*lt;
            float p0 = __expf(shh[j][0] + sxx[j][0]);
            float p1 = __expf(shh[j][1] + sxx[j][1]);
            float p2 = __expf(shh[j][2] + sxx[j][2]);
            float p3 = __expf(shh[j][3] + sxx[j][3]);
            if (domask){
                if (colLoc   > row0)     p0 = 0.0f;
                if (colLoc+1 > row0)     p1 = 0.0f;
                if (colLoc   > row0+8)   p2 = 0.0f;
                if (colLoc+1 > row0+8)   p3 = 0.0f;
            }
            lsum0 += p0 + p1;
            lsum1 += p2 + p3;
            uint32_t h01 = bf2pack(p0, p1), h23 = bf2pack(p2, p3);
            float h0 = __uint_as_float(h01<<16), h1 = __uint_as_float(h01 & 0xFFFF0000u);
            float h2 = __uint_as_float(h23<<16), h3 = __uint_as_float(h23 & 0xFFFF0000u);
            uint32_t l01 = bf2pack(p0-h0, p1-h1);
            uint32_t l23 = bf2pack(p2-h2, p3-h3);
            *reinterpret_cast<uint32_t*>(smc + OFF_PH + row0*PST     + colLoc*2) = h01;
            *reinterpret_cast<uint32_t*>(smc + OFF_PH + (row0+8)*PST + colLoc*2) = h23;
            *reinterpret_cast<uint32_t*>(smc + OFF_PL + row0*PST     + colLoc*2) = l01;
            *reinterpret_cast<uint32_t*>(smc + OFF_PL + (row0+8)*PST + colLoc*2) = l23;
        }
        __syncthreads();                            // P tile complete

        // ---- O += P V : full k (4 chunks) x this warp's d-quarter (32 cols) ----
        #pragma unroll
        for (int kc = 0; kc < 4; kc++){
            uint32_t pH[4], pL[4];
            ldsm4(pH, pa_h + kc*32);
            ldsm4(pL, pa_l + kc*32);
            #pragma unroll
            for (int jp = 0; jp < 2; jp++){
                uint32_t va = bo + 2*KBYTES + vrow + jp*(16*STV) + kc*32;
                uint32_t tv[4], tw[4];
                ldsm4(tv, va);
                ldsm4(tw, va + VBYTES);
                uint32_t vh0[2]={tv[0],tv[1]}, vh1[2]={tv[2],tv[3]};
                uint32_t vl0[2]={tw[0],tw[1]}, vl1[2]={tw[2],tw[3]};
                mma_bf16(o[2*jp],   pH, vh0);
                mma_bf16(o[2*jp],   pH, vl0);
                mma_bf16(o[2*jp],   pL, vh0);
                mma_bf16(o[2*jp+1], pH, vh1);
                mma_bf16(o[2*jp+1], pH, vl1);
                mma_bf16(o[2*jp+1], pL, vh1);
            }
        }
    }

    // ---- lsum reduce across the 4 k-quarters; output slices are disjoint ----
    lsum0 += __shfl_xor_sync(0xffffffffu, lsum0, 1);
    lsum0 += __shfl_xor_sync(0xffffffffu, lsum0, 2);
    lsum1 += __shfl_xor_sync(0xffffffffu, lsum1, 1);
    lsum1 += __shfl_xor_sync(0xffffffffu, lsum1, 2);

    float* lr = reinterpret_cast<float*>(smc + OFF_LR);    // 4 x [64]
    if (lt == 0){ lr[nh*64 + row0] = lsum0; lr[nh*64 + row0+8] = lsum1; }
    __syncthreads();
    const float li0 = 1.0f / (lr[row0]   + lr[64+row0]   + lr[128+row0]   + lr[192+row0]);
    const float li1 = 1.0f / (lr[row0+8] + lr[64+row0+8] + lr[128+row0+8] + lr[192+row0+8]);

    float* og0 = out + ((size_t)b*CW + qbase + row0)*DIM + 32*nh;
    float* og1 = og0 + 8*DIM;
    #pragma unroll
    for (int jd = 0; jd < 4; jd++){
        int col = 8*jd + 2*lt;
        *reinterpret_cast<float2*>(og0 + col) = make_float2(o[jd][0]*li0, o[jd][1]*li0);
        *reinterpret_cast<float2*>(og1 + col) = make_float2(o[jd][2]*li1, o[jd][3]*li1);
    }
}

// ============================================================================
extern "C" void kernel_launch(void* const* d_in, const int* in_sizes, int n_in,
                              void* d_out, int out_size)
{
    (void)in_sizes; (void)n_in; (void)out_size;
    const float* x  = (const float*)d_in[0];
    const float* wq = (const float*)d_in[1];
    const float* wk = (const float*)d_in[2];
    const float* wv = (const float*)d_in[3];
    const float* R  = (const float*)d_in[4];
    float* out = (float*)d_out;

    cudaFuncSetAttribute(qkv_rope_kernel,   cudaFuncAttributeMaxDynamicSharedMemorySize, SMEM_A);
    cudaFuncSetAttribute(attn_hmma_kernel,  cudaFuncAttributeMaxDynamicSharedMemorySize, SMEM_BB);

    prep_kernel<<<304, 512>>>(R, wq, wk, wv);
    qkv_rope_kernel<<<dim3(32, BATCH, 3), 256, SMEM_A>>>(x);
    attn_hmma_kernel<<<256, 512, SMEM_BB>>>(out);
}

// round 17
// speedup vs baseline: 1.0687x; 1.0350x over previous
#include <cuda_runtime.h>
#include <cuda_bf16.h>
#include <cstdint>

#define CW 2048
#define DIM 128
#define BATCH 8
typedef unsigned long long ull;

__device__ __nv_bfloat16 g_qh[BATCH*CW*DIM], g_ql[BATCH*CW*DIM];
__device__ __nv_bfloat16 g_kh[BATCH*CW*DIM], g_kl[BATCH*CW*DIM];
__device__ __nv_bfloat16 g_vth[BATCH*DIM*CW], g_vtl[BATCH*DIM*CW];
__device__ float g_cos[CW*64], g_sin[CW*64];
__device__ __nv_bfloat16 g_wh[3*DIM*DIM], g_wl[3*DIM*DIM];

// ---- helpers ----
__device__ __forceinline__ uint32_t bf2pack(float lo, float hi){   // low half <- lo
    uint32_t r; asm("cvt.rn.bf16x2.f32 %0, %1, %2;" : "=r"(r) : "f"(hi), "f"(lo)); return r;
}
__device__ __forceinline__ void cpa16s(uint32_t dst, const void* src){
    asm volatile("cp.async.cg.shared.global [%0], [%1], 16;" :: "r"(dst), "l"(src));
}
__device__ __forceinline__ void ldsm4(uint32_t* r, uint32_t a){
    asm volatile("ldmatrix.sync.aligned.m8n8.x4.shared.b16 {%0,%1,%2,%3}, [%4];"
        : "=r"(r[0]),"=r"(r[1]),"=r"(r[2]),"=r"(r[3]) : "r"(a));
}
__device__ __forceinline__ void mma_bf16(float* c, const uint32_t* a, const uint32_t* b){
    asm volatile("mma.sync.aligned.m16n8k16.row.col.f32.bf16.bf16.f32 "
        "{%0,%1,%2,%3}, {%4,%5,%6,%7}, {%8,%9}, {%0,%1,%2,%3};"
        : "+f"(c[0]),"+f"(c[1]),"+f"(c[2]),"+f"(c[3])
        : "r"(a[0]),"r"(a[1]),"r"(a[2]),"r"(a[3]),"r"(b[0]),"r"(b[1]));
}

// ============================================================================
// Kernel P: prep — gather RoPE cos/sin from R's diagonal AND convert W->bf16
// ============================================================================
__global__ void __launch_bounds__(512,2) prep_kernel(
    const float* __restrict__ R, const float* __restrict__ wq,
    const float* __restrict__ wk, const float* __restrict__ wv)
{
    const int g = blockIdx.x, tid = threadIdx.x;
    if (g < 256){
        int idx = g*512 + tid;                    // 0 .. 2048*64-1
        int m = idx >> 6, i = idx & 63;
        const float* base = R + (size_t)m*(DIM*DIM) + i*258;
        g_cos[idx] = base[0];
        g_sin[idx] = base[128];
    } else {
        int idx = (g-256)*512 + tid;              // 0 .. 24575 (pairs)
        int mat = idx >> 13;
        int rem = idx & 8191;
        const float* w = (mat==0)?wq:(mat==1)?wk:wv;
        float2 v = reinterpret_cast<const float2*>(w)[rem];
        uint32_t h = bf2pack(v.x, v.y);
        float h0 = __uint_as_float(h<<16), h1 = __uint_as_float(h & 0xFFFF0000u);
        reinterpret_cast<uint32_t*>(g_wh)[idx] = h;
        reinterpret_cast<uint32_t*>(g_wl)[idx] = bf2pack(v.x - h0, v.y - h1);
    }
}

// ============================================================================
// Kernel A: projection (+RoPE for Q/K) on HMMA (unchanged from R15)
// ============================================================================
#define AST 272
#define A_XH 0
#define A_XL 17408
#define A_WH 34816
#define A_WL 69632
#define SMEM_A 104448

__global__ void __launch_bounds__(256,2) qkv_rope_kernel(const float* __restrict__ x)
{
    extern __shared__ char smc[];
    const uint32_t sb = (uint32_t)__cvta_generic_to_shared(smc);
    const int tid = threadIdx.x, wid = tid>>5, lane = tid&31;
    const int b = blockIdx.y, mbase = blockIdx.x*64, mat = blockIdx.z;
    const int wg = wid & 3;
    const int nh = wid >> 2;
    const int l7 = lane & 7, lhi = lane >> 3;
    const int lg = lane >> 2, lt = lane & 3;

    {
        const char* wh = (const char*)g_wh + mat*32768;
        const char* wl = (const char*)g_wl + mat*32768;
        #pragma unroll
        for (int t = 0; t < 8; t++){
            int c = tid + t*256;
            int r = c>>4, cb = (c&15)*16;
            uint32_t dst = sb + A_WH + r*AST + cb;
            cpa16s(dst,                 wh + r*256 + cb);
            cpa16s(dst + (A_WL - A_WH), wl + r*256 + cb);
        }
        asm volatile("cp.async.commit_group;");
    }
    {
        const float* xg = x + ((size_t)b*CW + mbase)*DIM;
        uint32_t* xh = reinterpret_cast<uint32_t*>(smc);
        #pragma unroll
        for (int t = 0; t < 16; t++){
            int idx = tid + t*256;
            int r = idx>>6, cp = idx&63;
            float2 v = *reinterpret_cast<const float2*>(xg + r*DIM + 2*cp);
            uint32_t h = bf2pack(v.x, v.y);
            float h0 = __uint_as_float(h<<16), h1 = __uint_as_float(h & 0xFFFF0000u);
            uint32_t off = (uint32_t)(r*AST + cp*4) >> 2;
            xh[(A_XH>>2) + off] = h;
            xh[(A_XL>>2) + off] = bf2pack(v.x - h0, v.y - h1);
        }
    }
    asm volatile("cp.async.wait_group 0;");
    __syncthreads();

    uint32_t xhf[8][4], xlf[8][4];
    {
        uint32_t xa = sb + A_XH + (16*wg + (lane&15))*AST + (lane>>4)*16;
        #pragma unroll
        for (int c = 0; c < 8; c++){
            ldsm4(xhf[c], xa + c*32);
            ldsm4(xlf[c], xa + (A_XL - A_XH) + c*32);
        }
    }

    float s[8][4];
    #pragma unroll
    for (int j = 0; j < 8; j++){ s[j][0]=s[j][1]=s[j][2]=s[j][3]=0.0f; }
    #pragma unroll
    for (int j = 0; j < 8; j++){
        const int jj = 8*nh + j;
        uint32_t wa = sb + A_WH + (8*jj + l7)*AST + lhi*16;
        #pragma unroll
        for (int c2 = 0; c2 < 4; c2++){
            uint32_t th[4], tl[4];
            ldsm4(th, wa + c2*64);
            ldsm4(tl, wa + (A_WL - A_WH) + c2*64);
            uint32_t bhA[2]={th[0],th[1]}, bhB[2]={th[2],th[3]};
            uint32_t blA[2]={tl[0],tl[1]}, blB[2]={tl[2],tl[3]};
            mma_bf16(s[j], xhf[2*c2],   bhA);
            mma_bf16(s[j], xhf[2*c2+1], bhB);
            mma_bf16(s[j], xhf[2*c2],   blA);
            mma_bf16(s[j], xhf[2*c2+1], blB);
            mma_bf16(s[j], xlf[2*c2],   bhA);
            mma_bf16(s[j], xlf[2*c2+1], bhB);
        }
    }

    const int r0 = 16*wg + lg;
    if (mat < 2){
        const float qsc = (mat==0) ? 0.08838834764831845f : 1.0f;
        uint32_t* gh = reinterpret_cast<uint32_t*>(mat==0 ? g_qh : g_kh);
        uint32_t* gl = reinterpret_cast<uint32_t*>(mat==0 ? g_ql : g_kl);
        const int m0 = mbase + r0, m1 = m0 + 8;
        const float* cr0 = g_cos + (size_t)m0*64;
        const float* sr0 = g_sin + (size_t)m0*64;
        const float* cr1 = g_cos + (size_t)m1*64;
        const float* sr1 = g_sin + (size_t)m1*64;
        size_t rp0 = ((size_t)b*CW + m0)*64, rp1 = ((size_t)b*CW + m1)*64;
        #pragma unroll
        for (int j = 0; j < 8; j++){
            const int i = 32*nh + 4*j + lt;
            float c0 = __ldg(cr0 + i), s0 = __ldg(sr0 + i);
            float c1 = __ldg(cr1 + i), s1 = __ldg(sr1 + i);
            float a0 = ( s[j][0]*c0 + s[j][1]*s0)*qsc;
            float a1 = (-s[j][0]*s0 + s[j][1]*c0)*qsc;
            float b0 = ( s[j][2]*c1 + s[j][3]*s1)*qsc;
            float b1 = (-s[j][2]*s1 + s[j][3]*c1)*qsc;
            uint32_t ha = bf2pack(a0, a1);
            float ha0 = __uint_as_float(ha<<16), ha1 = __uint_as_float(ha & 0xFFFF0000u);
            gh[rp0 + i] = ha;
            gl[rp0 + i] = bf2pack(a0-ha0, a1-ha1);
            uint32_t hb = bf2pack(b0, b1);
            float hb0 = __uint_as_float(hb<<16), hb1 = __uint_as_float(hb & 0xFFFF0000u);
            gh[rp1 + i] = hb;
            gl[rp1 + i] = bf2pack(b0-hb0, b1-hb1);
        }
    } else {
        __syncthreads();
        unsigned short* vth_s = reinterpret_cast<unsigned short*>(smc);
        unsigned short* vtl_s = vth_s + 128*66;
        #pragma unroll
        for (int j = 0; j < 8; j++){
            const int d0 = 64*nh + 8*j + 2*lt;
            uint32_t h = bf2pack(s[j][0], s[j][1]);
            float h0 = __uint_as_float(h<<16), h1 = __uint_as_float(h & 0xFFFF0000u);
            uint32_t l = bf2pack(s[j][0]-h0, s[j][1]-h1);
            vth_s[d0*66 + r0]     = (unsigned short)(h & 0xFFFF);
            vth_s[(d0+1)*66 + r0] = (unsigned short)(h >> 16);
            vtl_s[d0*66 + r0]     = (unsigned short)(l & 0xFFFF);
            vtl_s[(d0+1)*66 + r0] = (unsigned short)(l >> 16);
            uint32_t g = bf2pack(s[j][2], s[j][3]);
            float g0 = __uint_as_float(g<<16), g1 = __uint_as_float(g & 0xFFFF0000u);
            uint32_t m = bf2pack(s[j][2]-g0, s[j][3]-g1);
            vth_s[d0*66 + r0+8]     = (unsigned short)(g & 0xFFFF);
            vth_s[(d0+1)*66 + r0+8] = (unsigned short)(g >> 16);
            vtl_s[d0*66 + r0+8]     = (unsigned short)(m & 0xFFFF);
            vtl_s[(d0+1)*66 + r0+8] = (unsigned short)(m >> 16);
        }
        __syncthreads();
        uint32_t* gh = reinterpret_cast<uint32_t*>(g_vth);
        uint32_t* gl = reinterpret_cast<uint32_t*>(g_vtl);
        for (int idx = tid; idx < 128*32; idx += 256){
            int d = idx>>5, mp = idx&31;
            size_t dst = ((size_t)(b*DIM + d)*CW + mbase)/2 + mp;
            gh[dst] = *reinterpret_cast<uint32_t*>(&vth_s[d*66 + 2*mp]);
            gl[dst] = *reinterpret_cast<uint32_t*>(&vtl_s[d*66 + 2*mp]);
        }
    }
}

// ============================================================================
// Kernel B: HMMA flash attention (R15 structure) with barrier surgery:
//   - prefetch moved AFTER the KV-ready full barrier (top barrier deleted)
//   - P-ready barrier is a named 128-thread barrier per row-block group wg
//   Per iteration: 1 full __syncthreads + 1 named bar.sync (was 3 full).
// ============================================================================
#define STK 272
#define STV 144
#define PST 144
#define KBYTES (64*STK)
#define VBYTES (128*STV)
#define QBYTES (64*STK)
#define OFF_Q  0
#define OFF_B0 (2*QBYTES)
#define OFF_B1 (OFF_B0 + 2*KBYTES + 2*VBYTES)
#define OFF_LR (OFF_B1 + 2*KBYTES + 2*VBYTES)
#define OFF_PH (OFF_LR + 1024)
#define OFF_PL (OFF_PH + 64*PST)
#define SMEM_BB (OFF_PL + 64*PST)

__device__ __forceinline__ void load_kv_stage(uint32_t sb, int b, int kt, int buf, int tid){
    const char* kh = (const char*)(g_kh  + ((size_t)b*CW + kt*64)*DIM);
    const char* kl = (const char*)(g_kl  + ((size_t)b*CW + kt*64)*DIM);
    const char* vh = (const char*)(g_vth + (size_t)b*DIM*CW + kt*64);
    const char* vl = (const char*)(g_vtl + (size_t)b*DIM*CW + kt*64);
    uint32_t bo = sb + (buf ? OFF_B1 : OFF_B0);
    #pragma unroll
    for (int t = 0; t < 2; t++){
        int c = tid + t*512;                   // K: 64 rows x 16 chunks
        int n = c>>4, cb = (c&15)*16;
        uint32_t dst = bo + n*STK + cb;
        cpa16s(dst,          kh + n*256 + cb);
        cpa16s(dst + KBYTES, kl + n*256 + cb);
    }
    #pragma unroll
    for (int t = 0; t < 2; t++){
        int c = tid + t*512;                   // V^T: 128 rows x 8 chunks
        int d = c>>3, cb = (c&7)*16;
        uint32_t dst = bo + 2*KBYTES + d*STV + cb;
        cpa16s(dst,          vh + (size_t)d*CW*2 + cb);
        cpa16s(dst + VBYTES, vl + (size_t)d*CW*2 + cb);
    }
}

__global__ void __launch_bounds__(512,1) attn_hmma_kernel(float* __restrict__ out)
{
    extern __shared__ char smc[];
    const uint32_t sb = (uint32_t)__cvta_generic_to_shared(smc);
    const int tid = threadIdx.x, wid = tid>>5, lane = tid&31;
    const int b = blockIdx.x & 7;
    const int qt = 31 - ((int)blockIdx.x >> 3);    // heavy q-tiles first
    const int qbase = qt*64;
    const int ktmax = qt;
    const int wg = wid & 3;                         // row block (16 rows)
    const int nh = wid >> 2;                        // k-quarter (QK) / d-quarter (PV)
    const int l7 = lane & 7;
    const int lg = lane >> 2, lt = lane & 3;
    const int row0 = 16*wg + lg;

    // ---- prologue: stage Q + K/V tile0 ----
    {
        const char* qh = (const char*)(g_qh + ((size_t)b*CW + qbase)*DIM);
        const char* ql = (const char*)(g_ql + ((size_t)b*CW + qbase)*DIM);
        #pragma unroll
        for (int t = 0; t < 2; t++){
            int c = tid + t*512;
            int n = c>>4, cb = (c&15)*16;
            uint32_t dst = sb + OFF_Q + n*STK + cb;
            cpa16s(dst,          qh + n*256 + cb);
            cpa16s(dst + QBYTES, ql + n*256 + cb);
        }
        asm volatile("cp.async.commit_group;");
        load_kv_stage(sb, b, 0, 0, tid);
        asm volatile("cp.async.commit_group;");
    }
    asm volatile("cp.async.wait_group 1;");        // Q landed
    __syncthreads();

    // ---- persistent Q A-fragments (8 k-chunks, hi+lo) ----
    uint32_t ah[8][4], al[8][4];
    {
        uint32_t qa = sb + OFF_Q + (16*wg + (lane&15))*STK + (lane>>4)*16;
        #pragma unroll
        for (int c = 0; c < 8; c++){
            ldsm4(ah[c], qa + c*32);
            ldsm4(al[c], qa + QBYTES + c*32);
        }
    }

    float o[4][4];
    #pragma unroll
    for (int jd = 0; jd < 4; jd++){
        #pragma unroll
        for (int i = 0; i < 4; i++) o[jd][i] = 0.0f;
    }
    float lsum0 = 0.0f, lsum1 = 0.0f;

    // lane-invariant address parts
    const uint32_t krow = (uint32_t)((8*(2*nh + (lane>>4)) + l7)*STK + ((lane>>3)&1)*16);
    const uint32_t vrow = (uint32_t)(((lane>>4)*8 + l7 + 32*nh)*STV + ((lane>>3)&1)*16);
    const uint32_t pra  = (uint32_t)((16*wg + (lane&15))*PST + (lane>>4)*16);
    const uint32_t pa_h = sb + OFF_PH + pra;
    const uint32_t pa_l = sb + OFF_PL + pra;

    for (int kt = 0; kt <= ktmax; kt++){
        asm volatile("cp.async.wait_group 0;");     // stage kt landed
        __syncthreads();                            // KV ready AND all PV(kt-1) done

        // prefetch kt+1 (writes buf[(kt+1)&1]; disjoint from this iter's reads,
        // and all readers of that buffer passed the barrier above)
        if (kt < ktmax) load_kv_stage(sb, b, kt+1, (kt+1)&1, tid);
        asm volatile("cp.async.commit_group;");

        const uint32_t bo = sb + ((kt&1) ? OFF_B1 : OFF_B0);
        const uint32_t ka = bo + krow;

        // ---- S = Q K^T over this warp's k-quarter (16 cols), 2 chains ----
        float shh[2][4], sxx[2][4];
        #pragma unroll
        for (int j = 0; j < 2; j++){
            #pragma unroll
            for (int i = 0; i < 4; i++){ shh[j][i] = 0.0f; sxx[j][i] = 0.0f; }
        }
        #pragma unroll
        for (int c = 0; c < 8; c++){
            uint32_t th[4], tl[4];
            ldsm4(th, ka + c*32);
            ldsm4(tl, ka + KBYTES + c*32);
            uint32_t bh0[2]={th[0],th[1]}, bh1[2]={th[2],th[3]};
            uint32_t bl0[2]={tl[0],tl[1]}, bl1[2]={tl[2],tl[3]};
            mma_bf16(shh[0], ah[c], bh0);
            mma_bf16(sxx[0], ah[c], bl0);
            mma_bf16(sxx[0], al[c], bh0);
            mma_bf16(shh[1], ah[c], bh1);
            mma_bf16(sxx[1], ah[c], bl1);
            mma_bf16(sxx[1], al[c], bh1);
        }

        // ---- softmax (unnormalized; Q pre-scaled) -> P hi/lo into smem ----
        const bool domask = (kt == ktmax);
        #pragma unroll
        for (int j = 0; j < 2; j++){
            const int colLoc = 16*nh + 8*j + 2*lt;
            float p0 = __expf(shh[j][0] + sxx[j][0]);
            float p1 = __expf(shh[j][1] + sxx[j][1]);
            float p2 = __expf(shh[j][2] + sxx[j][2]);
            float p3 = __expf(shh[j][3] + sxx[j][3]);
            if (domask){
                if (colLoc   > row0)     p0 = 0.0f;
                if (colLoc+1 > row0)     p1 = 0.0f;
                if (colLoc   > row0+8)   p2 = 0.0f;
                if (colLoc+1 > row0+8)   p3 = 0.0f;
            }
            lsum0 += p0 + p1;
            lsum1 += p2 + p3;
            uint32_t h01 = bf2pack(p0, p1), h23 = bf2pack(p2, p3);
            float h0 = __uint_as_float(h01<<16), h1 = __uint_as_float(h01 & 0xFFFF0000u);
            float h2 = __uint_as_float(h23<<16), h3 = __uint_as_float(h23 & 0xFFFF0000u);
            uint32_t l01 = bf2pack(p0-h0, p1-h1);
            uint32_t l23 = bf2pack(p2-h2, p3-h3);
            *reinterpret_cast<uint32_t*>(smc + OFF_PH + row0*PST     + colLoc*2) = h01;
            *reinterpret_cast<uint32_t*>(smc + OFF_PH + (row0+8)*PST + colLoc*2) = h23;
            *reinterpret_cast<uint32_t*>(smc + OFF_PL + row0*PST     + colLoc*2) = l01;
            *reinterpret_cast<uint32_t*>(smc + OFF_PL + (row0+8)*PST + colLoc*2) = l23;
        }
        // P rows [16wg, 16wg+16) are produced and consumed ONLY by the 4 warps
        // sharing wg -> named 128-thread barrier per group (ids 4..7)
        asm volatile("bar.sync %0, %1;" :: "r"(4 + wg), "r"(128) : "memory");

        // ---- O += P V : full k (4 chunks) x this warp's d-quarter (32 cols) ----
        #pragma unroll
        for (int kc = 0; kc < 4; kc++){
            uint32_t pH[4], pL[4];
            ldsm4(pH, pa_h + kc*32);
            ldsm4(pL, pa_l + kc*32);
            #pragma unroll
            for (int jp = 0; jp < 2; jp++){
                uint32_t va = bo + 2*KBYTES + vrow + jp*(16*STV) + kc*32;
                uint32_t tv[4], tw[4];
                ldsm4(tv, va);
                ldsm4(tw, va + VBYTES);
                uint32_t vh0[2]={tv[0],tv[1]}, vh1[2]={tv[2],tv[3]};
                uint32_t vl0[2]={tw[0],tw[1]}, vl1[2]={tw[2],tw[3]};
                mma_bf16(o[2*jp],   pH, vh0);
                mma_bf16(o[2*jp],   pH, vl0);
                mma_bf16(o[2*jp],   pL, vh0);
                mma_bf16(o[2*jp+1], pH, vh1);
                mma_bf16(o[2*jp+1], pH, vl1);
                mma_bf16(o[2*jp+1], pL, vh1);
            }
        }
    }

    // ---- lsum reduce across the 4 k-quarters; output slices are disjoint ----
    lsum0 += __shfl_xor_sync(0xffffffffu, lsum0, 1);
    lsum0 += __shfl_xor_sync(0xffffffffu, lsum0, 2);
    lsum1 += __shfl_xor_sync(0xffffffffu, lsum1, 1);
    lsum1 += __shfl_xor_sync(0xffffffffu, lsum1, 2);

    float* lr = reinterpret_cast<float*>(smc + OFF_LR);    // 4 x [64]
    if (lt == 0){ lr[nh*64 + row0] = lsum0; lr[nh*64 + row0+8] = lsum1; }
    __syncthreads();
    const float li0 = 1.0f / (lr[row0]   + lr[64+row0]   + lr[128+row0]   + lr[192+row0]);
    const float li1 = 1.0f / (lr[row0+8] + lr[64+row0+8] + lr[128+row0+8] + lr[192+row0+8]);

    float* og0 = out + ((size_t)b*CW + qbase + row0)*DIM + 32*nh;
    float* og1 = og0 + 8*DIM;
    #pragma unroll
    for (int jd = 0; jd < 4; jd++){
        int col = 8*jd + 2*lt;
        *reinterpret_cast<float2*>(og0 + col) = make_float2(o[jd][0]*li0, o[jd][1]*li0);
        *reinterpret_cast<float2*>(og1 + col) = make_float2(o[jd][2]*li1, o[jd][3]*li1);
    }
}

// ============================================================================
extern "C" void kernel_launch(void* const* d_in, const int* in_sizes, int n_in,
                              void* d_out, int out_size)
{
    (void)in_sizes; (void)n_in; (void)out_size;
    const float* x  = (const float*)d_in[0];
    const float* wq = (const float*)d_in[1];
    const float* wk = (const float*)d_in[2];
    const float* wv = (const float*)d_in[3];
    const float* R  = (const float*)d_in[4];
    float* out = (float*)d_out;

    cudaFuncSetAttribute(qkv_rope_kernel,   cudaFuncAttributeMaxDynamicSharedMemorySize, SMEM_A);
    cudaFuncSetAttribute(attn_hmma_kernel,  cudaFuncAttributeMaxDynamicSharedMemorySize, SMEM_BB);

    prep_kernel<<<304, 512>>>(R, wq, wk, wv);
    qkv_rope_kernel<<<dim3(32, BATCH, 3), 256, SMEM_A>>>(x);
    attn_hmma_kernel<<<256, 512, SMEM_BB>>>(out);
}